// round 16
// baseline (speedup 1.0000x reference)
#include <cuda_runtime.h>

#define DIM 768
#define NE 8
#define WARPS_PER_BLOCK 8
#define THREADS 256
#define TOK_PER_WARP 4
#define TOK_PER_BLOCK (WARPS_PER_BLOCK * TOK_PER_WARP)  // 32
// DIM/4 = 192 float4 per token row; 192/32 lanes = 6 float4 per lane
#define F4_PER_LANE 6

// ---- packed f32x2 helpers (FFMA2: ptxas never emits this from C++) ----
__device__ __forceinline__ unsigned long long pk2(float lo, float hi) {
    unsigned long long r;
    asm("mov.b64 %0, {%1, %2};" : "=l"(r) : "f"(lo), "f"(hi));
    return r;
}
__device__ __forceinline__ unsigned long long fma2(unsigned long long a,
                                                   unsigned long long b,
                                                   unsigned long long c) {
    unsigned long long d;
    asm("fma.rn.f32x2 %0, %1, %2, %3;" : "=l"(d) : "l"(a), "l"(b), "l"(c));
    return d;
}
__device__ __forceinline__ float upk_sum(unsigned long long p) {
    float lo, hi;
    asm("mov.b64 {%0, %1}, %2;" : "=f"(lo), "=f"(hi) : "l"(p));
    return lo + hi;
}

__global__ __launch_bounds__(THREADS, 4)   // caps regs at 64 -> 4 CTAs/SM
void router_kernel(const float* __restrict__ x,
                   const float* __restrict__ W,
                   const float* __restrict__ b,
                   float* __restrict__ out,
                   int n_tokens, int write_idx)
{
    __shared__ float Ws[NE * DIM];
    __shared__ float bs[NE];

    // Stage W (24 KB) + b into shared once per block, vectorized.
    {
        const float4* Wg = reinterpret_cast<const float4*>(W);
        float4* Wsm = reinterpret_cast<float4*>(Ws);
        #pragma unroll
        for (int i = threadIdx.x; i < NE * DIM / 4; i += THREADS)
            Wsm[i] = Wg[i];
        if (threadIdx.x < NE) bs[threadIdx.x] = b[threadIdx.x];
    }
    __syncthreads();

    const int warp = threadIdx.x >> 5;
    const int lane = threadIdx.x & 31;
    int token0 = (blockIdx.x * WARPS_PER_BLOCK + warp) * TOK_PER_WARP;
    if (token0 >= n_tokens) return;   // after the only __syncthreads: safe

    // Tail: shift window back so all 4 tokens are in-bounds (no-op for
    // 25216 % 32 == 0; idempotent recompute on ragged shapes).
    if (token0 > n_tokens - TOK_PER_WARP) token0 = n_tokens - TOK_PER_WARP;

    const float4* xb = reinterpret_cast<const float4*>(x) +
                       (size_t)token0 * (DIM / 4) + lane;
    const float4* wb = reinterpret_cast<const float4*>(Ws) + lane;

    // Packed accumulators: a2[t*8+e] holds {even,odd} partial sums.
    // 16 pairs = 32 regs, same as the scalar version.
    unsigned long long a2[TOK_PER_WARP * NE];
    const unsigned long long z2 = pk2(0.0f, 0.0f);
    #pragma unroll
    for (int j = 0; j < TOK_PER_WARP * NE; j++) a2[j] = z2;

    // Mainloop: per i, 4 coalesced streaming LDG.128 (x, no-reuse ->
    // __ldcs), 8 LDS.128 (W amortized over 4 tokens), and 64 FFMA2
    // (vs 128 FFMA scalar: halves FMA issue time, ~8.6us -> ~4.3us chip-wide).
    #pragma unroll
    for (int i = 0; i < F4_PER_LANE; i++) {
        unsigned long long xlo[TOK_PER_WARP], xhi[TOK_PER_WARP];
        #pragma unroll
        for (int t = 0; t < TOK_PER_WARP; t++) {
            const float4 xv = __ldcs(&xb[t * (DIM / 4) + i * 32]);
            xlo[t] = pk2(xv.x, xv.y);
            xhi[t] = pk2(xv.z, xv.w);
        }
        #pragma unroll
        for (int e = 0; e < NE; e++) {
            const float4 wv = wb[e * (DIM / 4) + i * 32];
            const unsigned long long wlo = pk2(wv.x, wv.y);
            const unsigned long long whi = pk2(wv.z, wv.w);
            #pragma unroll
            for (int t = 0; t < TOK_PER_WARP; t++) {
                a2[t * NE + e] = fma2(xlo[t], wlo, a2[t * NE + e]);
                a2[t * NE + e] = fma2(xhi[t], whi, a2[t * NE + e]);
            }
        }
    }

    // Collapse packed pairs -> scalar per-slot partials.
    float v[TOK_PER_WARP * NE];
    #pragma unroll
    for (int j = 0; j < TOK_PER_WARP * NE; j++) v[j] = upk_sum(a2[j]);

    // Warp transpose-reduce: 32 slots -> 32 lanes in 31 shuffles.
    // Final: lane L holds the warp-wide sum of slot L.
    #pragma unroll
    for (int off = 16; off > 0; off >>= 1) {
        #pragma unroll
        for (int j = 0; j < off; j++) {
            const bool hi = (lane & off) != 0;
            float send = hi ? v[j] : v[j + off];
            float other = __shfl_xor_sync(0xffffffffu, send, off);
            v[j] = (hi ? v[j + off] : v[j]) + other;
        }
    }

    // Lane L owns the logit for token t = L>>3, expert e = L&7.
    const int t = lane >> 3;
    const int e = lane & 7;
    const int token = token0 + t;

    float logit = v[0] + bs[e];

    // Softmax over the 8-lane expert group (3+3 shuffles).
    float m = logit;
    #pragma unroll
    for (int off = 4; off > 0; off >>= 1)
        m = fmaxf(m, __shfl_xor_sync(0xffffffffu, m, off));
    float ex = __expf(logit - m);
    float s = ex;
    #pragma unroll
    for (int off = 4; off > 0; off >>= 1)
        s += __shfl_xor_sync(0xffffffffu, s, off);
    const float gate = ex / s;

    // Top-1 with lowest-index tie-break (matches jax.lax.top_k).
    float bv = gate; int bi = e;
    #pragma unroll
    for (int off = 4; off > 0; off >>= 1) {
        float ov = __shfl_xor_sync(0xffffffffu, bv, off);
        int   oi = __shfl_xor_sync(0xffffffffu, bi, off);
        if (ov > bv || (ov == bv && oi < bi)) { bv = ov; bi = oi; }
    }
    // Top-2: exclude the winner (gates > 0, so -1 is a safe sentinel).
    float cv = (e == bi) ? -1.0f : gate; int ci = e;
    #pragma unroll
    for (int off = 4; off > 0; off >>= 1) {
        float ov = __shfl_xor_sync(0xffffffffu, cv, off);
        int   oi = __shfl_xor_sync(0xffffffffu, ci, off);
        if (ov > cv || (ov == cv && oi < ci)) { cv = ov; ci = oi; }
    }

    // One writer lane per token group.
    if (e == 0) {
        out[(size_t)token * 2 + 0] = bv;
        out[(size_t)token * 2 + 1] = cv;
        if (write_idx) {
            float* oi = out + (size_t)n_tokens * 2;
            oi[(size_t)token * 2 + 0] = (float)bi;   // float(int) exact
            oi[(size_t)token * 2 + 1] = (float)ci;
        }
    }
}

extern "C" void kernel_launch(void* const* d_in, const int* in_sizes, int n_in,
                              void* d_out, int out_size) {
    const float* x = (const float*)d_in[0];  // [128,197,768]
    const float* W = (const float*)d_in[1];  // [8,768]
    const float* b = (const float*)d_in[2];  // [8]
    float* out = (float*)d_out;

    const int n_tokens = in_sizes[0] / DIM;            // 25216
    const int write_idx = (out_size >= 4 * n_tokens);  // tuple packed: gates then idx

    const int grid = (n_tokens + TOK_PER_BLOCK - 1) / TOK_PER_BLOCK;  // 788
    router_kernel<<<grid, THREADS>>>(x, W, b, out, n_tokens, write_idx);
}

// round 17
// speedup vs baseline: 2.4189x; 2.4189x over previous
#include <cuda_runtime.h>

#define DIM 768
#define NE 8
#define WARPS_PER_BLOCK 8
#define THREADS 256
#define TOK_PER_WARP 4
#define TOK_PER_BLOCK (WARPS_PER_BLOCK * TOK_PER_WARP)  // 32
// DIM/4 = 192 float4 per token row; 192/32 lanes = 6 float4 per lane
#define F4_PER_LANE 6

__global__ __launch_bounds__(THREADS, 4)   // caps regs at 64 -> 4 CTAs/SM
void router_kernel(const float* __restrict__ x,
                   const float* __restrict__ W,
                   const float* __restrict__ b,
                   float* __restrict__ out,
                   int n_tokens, int write_idx)
{
    __shared__ float Ws[NE * DIM];
    __shared__ float bs[NE];

    // Stage W (24 KB) + b into shared once per block, vectorized.
    {
        const float4* Wg = reinterpret_cast<const float4*>(W);
        float4* Wsm = reinterpret_cast<float4*>(Ws);
        #pragma unroll
        for (int i = threadIdx.x; i < NE * DIM / 4; i += THREADS)
            Wsm[i] = Wg[i];
        if (threadIdx.x < NE) bs[threadIdx.x] = b[threadIdx.x];
    }
    __syncthreads();

    const int warp = threadIdx.x >> 5;
    const int lane = threadIdx.x & 31;
    int token0 = (blockIdx.x * WARPS_PER_BLOCK + warp) * TOK_PER_WARP;
    if (token0 >= n_tokens) return;   // after the only __syncthreads: safe

    // Tail: shift window back so all 4 tokens are in-bounds (no-op for
    // 25216 % 32 == 0; idempotent recompute on ragged shapes).
    if (token0 > n_tokens - TOK_PER_WARP) token0 = n_tokens - TOK_PER_WARP;

    // Single base pointer; per-(t,i) displacements are compile-time
    // immediates in the LDG encoding -> minimal address registers.
    const float4* xb = reinterpret_cast<const float4*>(x) +
                       (size_t)token0 * (DIM / 4) + lane;
    const float4* wb = reinterpret_cast<const float4*>(Ws) + lane;

    // Register-free MLP: prefetch this warp's entire x working set (24
    // 128B-line groups, 12 KB) into L2 up front. No destination registers,
    // so memory-level parallelism is decoupled from the 64-reg cap; the
    // mainloop LDGs then complete at L2-hit latency (~240cyc) instead of
    // DRAM latency (~577cyc), which 32 warps/SM can hide.
    #pragma unroll
    for (int t = 0; t < TOK_PER_WARP; t++)
        #pragma unroll
        for (int i = 0; i < F4_PER_LANE; i++)
            asm volatile("prefetch.global.L2 [%0];" ::
                         "l"(xb + t * (DIM / 4) + i * 32));

    // Flat accumulators: v[t*8 + e]. After the transpose-reduce,
    // lane L holds the full sum of v[L].
    float v[TOK_PER_WARP * NE];
    #pragma unroll
    for (int j = 0; j < TOK_PER_WARP * NE; j++) v[j] = 0.0f;

    // Mainloop: per i, 4 independent coalesced LDG.128 (x stream) and
    // 8 LDS.128 (W, amortized over 4 tokens), 32 scalar float4-dots.
    #pragma unroll
    for (int i = 0; i < F4_PER_LANE; i++) {
        float4 xv[TOK_PER_WARP];
        #pragma unroll
        for (int t = 0; t < TOK_PER_WARP; t++)
            xv[t] = xb[t * (DIM / 4) + i * 32];
        #pragma unroll
        for (int e = 0; e < NE; e++) {
            const float4 wv = wb[e * (DIM / 4) + i * 32];
            #pragma unroll
            for (int t = 0; t < TOK_PER_WARP; t++)
                v[t * NE + e] += xv[t].x * wv.x + xv[t].y * wv.y +
                                 xv[t].z * wv.z + xv[t].w * wv.w;
        }
    }

    // Warp transpose-reduce: 32 slots -> 32 lanes in 31 shuffles.
    // Final: lane L holds the warp-wide sum of slot L.
    #pragma unroll
    for (int off = 16; off > 0; off >>= 1) {
        #pragma unroll
        for (int j = 0; j < off; j++) {
            const bool hi = (lane & off) != 0;
            float send = hi ? v[j] : v[j + off];
            float other = __shfl_xor_sync(0xffffffffu, send, off);
            v[j] = (hi ? v[j + off] : v[j]) + other;
        }
    }

    // Lane L owns the logit for token t = L>>3, expert e = L&7.
    const int t = lane >> 3;
    const int e = lane & 7;
    const int token = token0 + t;

    float logit = v[0] + bs[e];

    // Softmax over the 8-lane expert group (3+3 shuffles).
    float m = logit;
    #pragma unroll
    for (int off = 4; off > 0; off >>= 1)
        m = fmaxf(m, __shfl_xor_sync(0xffffffffu, m, off));
    float ex = __expf(logit - m);
    float s = ex;
    #pragma unroll
    for (int off = 4; off > 0; off >>= 1)
        s += __shfl_xor_sync(0xffffffffu, s, off);
    const float gate = ex / s;

    // Top-1 with lowest-index tie-break (matches jax.lax.top_k).
    float bv = gate; int bi = e;
    #pragma unroll
    for (int off = 4; off > 0; off >>= 1) {
        float ov = __shfl_xor_sync(0xffffffffu, bv, off);
        int   oi = __shfl_xor_sync(0xffffffffu, bi, off);
        if (ov > bv || (ov == bv && oi < bi)) { bv = ov; bi = oi; }
    }
    // Top-2: exclude the winner (gates > 0, so -1 is a safe sentinel).
    float cv = (e == bi) ? -1.0f : gate; int ci = e;
    #pragma unroll
    for (int off = 4; off > 0; off >>= 1) {
        float ov = __shfl_xor_sync(0xffffffffu, cv, off);
        int   oi = __shfl_xor_sync(0xffffffffu, ci, off);
        if (ov > cv || (ov == cv && oi < ci)) { cv = ov; ci = oi; }
    }

    // One writer lane per token group.
    if (e == 0) {
        out[(size_t)token * 2 + 0] = bv;
        out[(size_t)token * 2 + 1] = cv;
        if (write_idx) {
            float* oi = out + (size_t)n_tokens * 2;
            oi[(size_t)token * 2 + 0] = (float)bi;   // float(int) exact
            oi[(size_t)token * 2 + 1] = (float)ci;
        }
    }
}

extern "C" void kernel_launch(void* const* d_in, const int* in_sizes, int n_in,
                              void* d_out, int out_size) {
    const float* x = (const float*)d_in[0];  // [128,197,768]
    const float* W = (const float*)d_in[1];  // [8,768]
    const float* b = (const float*)d_in[2];  // [8]
    float* out = (float*)d_out;

    const int n_tokens = in_sizes[0] / DIM;            // 25216
    const int write_idx = (out_size >= 4 * n_tokens);  // tuple packed: gates then idx

    const int grid = (n_tokens + TOK_PER_BLOCK - 1) / TOK_PER_BLOCK;  // 788
    router_kernel<<<grid, THREADS>>>(x, W, b, out, n_tokens, write_idx);
}